// round 15
// baseline (speedup 1.0000x reference)
#include <cuda_runtime.h>
#include <cuda_fp16.h>
#include <cstdint>

#define NB 16
#define NS 2048
#define ND 64
#define NO 128
#define NCTA 256

// ---------------- scratch (no allocs allowed) ------------------------------
__device__ float    g_Y[NB * NO * ND];     // fp32 Y, RED-accumulated
__device__ __half   g_wh[NO * NS];         // W fp16
__device__ unsigned g_cnt = 0;             // grid-barrier arrivals
__device__ unsigned g_epoch = 0;           // grid-barrier epoch (monotonic)

// ---------------- helpers --------------------------------------------------
__device__ __forceinline__ uint32_t smem_u32(const void* p) {
    uint32_t a;
    asm("{ .reg .u64 t; cvta.to.shared.u64 t, %1; cvt.u32.u64 %0, t; }"
        : "=r"(a) : "l"(p));
    return a;
}
__device__ __forceinline__ void ldm_x4(uint32_t* r, uint32_t addr) {
    asm volatile("ldmatrix.sync.aligned.m8n8.x4.shared.b16 {%0,%1,%2,%3}, [%4];"
                 : "=r"(r[0]), "=r"(r[1]), "=r"(r[2]), "=r"(r[3]) : "r"(addr));
}
__device__ __forceinline__ void ldm_x4t(uint32_t* r, uint32_t addr) {
    asm volatile("ldmatrix.sync.aligned.m8n8.x4.trans.shared.b16 {%0,%1,%2,%3}, [%4];"
                 : "=r"(r[0]), "=r"(r[1]), "=r"(r[2]), "=r"(r[3]) : "r"(addr));
}
__device__ __forceinline__ void mma_f16(float* c, const uint32_t* a,
                                        const uint32_t* b) {
    asm volatile(
        "mma.sync.aligned.m16n8k16.row.col.f32.f16.f16.f32 "
        "{%0,%1,%2,%3}, {%4,%5,%6,%7}, {%8,%9}, {%0,%1,%2,%3};"
        : "+f"(c[0]), "+f"(c[1]), "+f"(c[2]), "+f"(c[3])
        : "r"(a[0]), "r"(a[1]), "r"(a[2]), "r"(a[3]), "r"(b[0]), "r"(b[1]));
}
__device__ __forceinline__ void cp_async16(uint32_t saddr, const void* g) {
    asm volatile("cp.async.cg.shared.global [%0], [%1], 16;"
                 :: "r"(saddr), "l"(g) : "memory");
}
#define CP_COMMIT() asm volatile("cp.async.commit_group;" ::: "memory")
#define CP_WAIT(n)  asm volatile("cp.async.wait_group %0;" :: "n"(n) : "memory")

__device__ __forceinline__ void red_f32(float* p, float v) {
    asm volatile("red.global.add.f32 [%0], %1;" :: "l"(p), "f"(v) : "memory");
}
__device__ __forceinline__ uint32_t hpack2(float a, float b) {
    __half2 h = __floats2half2_rn(a, b);
    return *(uint32_t*)&h;
}

// Epoch-based grid barrier. Safe: all NCTA CTAs are guaranteed co-resident
// (2 CTAs/SM x 148 SMs = 296 >= 256). Epoch is monotonic across graph
// replays (relative compare), counter resets before each release.
__device__ __forceinline__ void gbar() {
    __threadfence();
    __syncthreads();
    if (threadIdx.x == 0) {
        unsigned my;
        asm volatile("ld.acquire.gpu.global.u32 %0, [%1];"
                     : "=r"(my) : "l"(&g_epoch));
        unsigned old = atomicAdd(&g_cnt, 1);
        if (old == NCTA - 1) {
            g_cnt = 0;
            asm volatile("red.release.gpu.global.add.u32 [%0], 1;"
                         :: "l"(&g_epoch) : "memory");
        } else {
            unsigned v;
            do {
                asm volatile("ld.acquire.gpu.global.u32 %0, [%1];"
                             : "=r"(v) : "l"(&g_epoch));
            } while (v == my);
        }
    }
    __syncthreads();
}

// smem layout (shared across phases; 52KB, 2 CTAs/SM)
#define P1_WAHI 0
#define P1_XBHI 34816
#define P2_XHI  0
#define P2_YHI  18432
#define P2_BIAS 36864
#define SMEM_SZ 53248

// ===========================================================================
// Fused kernel: grid (16 tiles, 16 b), 256 thr, one launch.
// P0: W fp32->fp16 + zero g_Y.  gbar.
// P1: g_Y[b] += W[o,kslice] @ x[b,kslice,d]  (1-term fp16 HMMA, RED).  gbar.
// P2: out[b][s-tile][o] = x @ Y^T + bias.
// ===========================================================================
__global__ __launch_bounds__(256, 2) void fused(const float* __restrict__ x,
                                                const float* __restrict__ W,
                                                const float* __restrict__ bias,
                                                float* __restrict__ out) {
    extern __shared__ char sm[];
    const int tid = threadIdx.x, wid = tid >> 5, lane = tid & 31;
    const int t = blockIdx.x, b = blockIdx.y;
    const int cta = b * 16 + t;
    const int wm = wid & 3, wn = wid >> 2;

    // ---------------- P0: convert W + zero Y --------------------------------
    {
        size_t e = (size_t)cta * 256 + tid;            // 65536 float4 of W
        float4 v = ((const float4*)W)[e];
        ((uint2*)g_wh)[e] = make_uint2(hpack2(v.x, v.y), hpack2(v.z, v.w));
        if (tid < 128)
            ((float4*)g_Y)[cta * 128 + tid] = make_float4(0.f, 0.f, 0.f, 0.f);
    }
    gbar();

    // ---------------- P1: g1 (ks = t) ---------------------------------------
    {
        const int o0 = wm * 32, d0 = wn * 32;
        const int kbase = t * 128;
        const uint32_t s_wahi = smem_u32(sm + P1_WAHI);
        const uint32_t s_xbhi = smem_u32(sm + P1_XBHI);

        // W phase-1 + phase-2 cp.async fp16 streams
#pragma unroll
        for (int j = 0; j < 4; j++) {
            int idx = tid + j * 256;
            int o = idx >> 3, c = idx & 7;
            cp_async16(s_wahi + o * 272 + c * 16,
                       &g_wh[(size_t)o * NS + kbase + c * 8]);
        }
        CP_COMMIT();
#pragma unroll
        for (int j = 0; j < 4; j++) {
            int idx = tid + j * 256;
            int o = idx >> 3, c = (idx & 7) + 8;
            cp_async16(s_wahi + o * 272 + c * 16,
                       &g_wh[(size_t)o * NS + kbase + c * 8]);
        }
        CP_COMMIT();

        // x tile [128 k][64 d] fp32 inline, 2 batches, overlaps W stream
#pragma unroll
        for (int batch = 0; batch < 2; batch++) {
            float4 v[4];
#pragma unroll
            for (int j = 0; j < 4; j++) {
                int idx = tid + (batch * 4 + j) * 256;
                int k = idx >> 4, d4 = (idx & 15) * 4;
                v[j] = *(const float4*)(x + ((size_t)b * NS + kbase + k) * ND + d4);
            }
#pragma unroll
            for (int j = 0; j < 4; j++) {
                int idx = tid + (batch * 4 + j) * 256;
                int k = idx >> 4, d4 = (idx & 15) * 4;
                *(uint2*)(sm + P1_XBHI + k * 144 + d4 * 2) =
                    make_uint2(hpack2(v[j].x, v[j].y), hpack2(v[j].z, v[j].w));
            }
        }

        float acc[2][4][4];
#pragma unroll
        for (int mt = 0; mt < 2; mt++)
#pragma unroll
            for (int nt = 0; nt < 4; nt++)
#pragma unroll
                for (int q = 0; q < 4; q++) acc[mt][nt][q] = 0.f;

        CP_WAIT(1);
        __syncthreads();

#pragma unroll
        for (int half = 0; half < 2; half++) {
#pragma unroll
            for (int k2 = 0; k2 < 4; k2++) {
                const int kk = half * 4 + k2;
                uint32_t ahi[2][4];
#pragma unroll
                for (int mt = 0; mt < 2; mt++) {
                    uint32_t off = (uint32_t)((o0 + mt * 16 + (lane & 15)) * 272 +
                                              kk * 32 + (lane >> 4) * 16);
                    ldm_x4(ahi[mt], s_wahi + off);
                }
                uint32_t bhi[2][4];
#pragma unroll
                for (int p = 0; p < 2; p++) {
                    uint32_t off = (uint32_t)((kk * 16 + (lane & 15)) * 144 +
                                              (d0 + p * 16 + (lane >> 4) * 8) * 2);
                    ldm_x4t(bhi[p], s_xbhi + off);
                }
#pragma unroll
                for (int mt = 0; mt < 2; mt++)
#pragma unroll
                    for (int nt = 0; nt < 4; nt++)
                        mma_f16(acc[mt][nt], ahi[mt], &bhi[nt >> 1][(nt & 1) * 2]);
            }
            if (half == 0) {
                CP_WAIT(0);
                __syncthreads();
            }
        }

        // RED-accumulate into g_Y
        float* Yp = g_Y + (size_t)b * NO * ND;
#pragma unroll
        for (int mt = 0; mt < 2; mt++)
#pragma unroll
            for (int nt = 0; nt < 4; nt++) {
                int o = o0 + mt * 16 + (lane >> 2);
                int d = d0 + nt * 8 + (lane & 3) * 2;
                float* p = Yp + (size_t)o * ND + d;
                red_f32(p, acc[mt][nt][0]);
                red_f32(p + 1, acc[mt][nt][1]);
                red_f32(p + 8 * ND, acc[mt][nt][2]);
                red_f32(p + 8 * ND + 1, acc[mt][nt][3]);
            }
    }
    gbar();

    // ---------------- P2: g2 (st = t) ---------------------------------------
    {
        float* bias_s = (float*)(sm + P2_BIAS);
        const int s0 = t * 128;
        const int s0w = wm * 16, o0w = wn * 64;
        const uint32_t s_xhi = smem_u32(sm + P2_XHI);
        const uint32_t s_yhi = smem_u32(sm + P2_YHI);

        // x tile [128 s][64 d] fp32 — front-batched for MLP
        float4 xv[8];
#pragma unroll
        for (int j = 0; j < 8; j++) {
            int idx = tid + j * 256;
            int s = idx >> 4, d4 = (idx & 15) * 4;
            xv[j] = *(const float4*)(x + ((size_t)b * NS + s0 + s) * ND + d4);
        }
        // Y tile [128 o][64 d] fp32 (L2-hot from P1 REDs)
        const float4* yg = (const float4*)(g_Y + (size_t)b * NO * ND);
#pragma unroll
        for (int j = 0; j < 8; j++) {
            int idx = tid + j * 256;
            int o = idx >> 4, d4 = (idx & 15) * 4;
            float4 v = yg[idx];
            *(uint2*)(sm + P2_YHI + o * 144 + d4 * 2) =
                make_uint2(hpack2(v.x, v.y), hpack2(v.z, v.w));
        }
#pragma unroll
        for (int j = 0; j < 8; j++) {
            int idx = tid + j * 256;
            int s = idx >> 4, d4 = (idx & 15) * 4;
            *(uint2*)(sm + P2_XHI + s * 144 + d4 * 2) =
                make_uint2(hpack2(xv[j].x, xv[j].y), hpack2(xv[j].z, xv[j].w));
        }
        if (tid < NO) bias_s[tid] = bias[tid];
        __syncthreads();

        float acc[2][8][4];
#pragma unroll
        for (int mt = 0; mt < 2; mt++)
#pragma unroll
            for (int nt = 0; nt < 8; nt++)
#pragma unroll
                for (int q = 0; q < 4; q++) acc[mt][nt][q] = 0.f;

#pragma unroll
        for (int kk = 0; kk < 4; kk++) {
            uint32_t ahi[2][4];
#pragma unroll
            for (int mt = 0; mt < 2; mt++) {
                uint32_t off = (uint32_t)((s0w + mt * 64 + (lane & 15)) * 144 +
                                          kk * 32 + (lane >> 4) * 16);
                ldm_x4(ahi[mt], s_xhi + off);
            }
            uint32_t bhi[4][4];
#pragma unroll
            for (int p = 0; p < 4; p++) {
                uint32_t off = (uint32_t)((o0w + p * 16 + (lane >> 4) * 8 + (lane & 7)) * 144 +
                                          kk * 32 + ((lane >> 3) & 1) * 16);
                ldm_x4(bhi[p], s_yhi + off);
            }
#pragma unroll
            for (int mt = 0; mt < 2; mt++)
#pragma unroll
                for (int nt = 0; nt < 8; nt++)
                    mma_f16(acc[mt][nt], ahi[mt], &bhi[nt >> 1][(nt & 1) * 2]);
        }

        // epilogue: +bias -> out
#pragma unroll
        for (int mt = 0; mt < 2; mt++) {
            const int srow = s0 + s0w + mt * 64 + (lane >> 2);
#pragma unroll
            for (int nt = 0; nt < 8; nt++) {
                int o = o0w + nt * 8 + (lane & 3) * 2;
                float2 bb = *(float2*)&bias_s[o];
                float* p0 = out + ((size_t)b * NS + srow) * NO + o;
                *(float2*)p0 =
                    make_float2(acc[mt][nt][0] + bb.x, acc[mt][nt][1] + bb.y);
                *(float2*)(p0 + 8 * NO) =
                    make_float2(acc[mt][nt][2] + bb.x, acc[mt][nt][3] + bb.y);
            }
        }
    }
}

// ===========================================================================
extern "C" void kernel_launch(void* const* d_in, const int* in_sizes, int n_in,
                              void* d_out, int out_size) {
    const float* x = nullptr;
    const float* W = nullptr;
    const float* bias = nullptr;
    for (int i = 0; i < n_in; i++) {
        if (in_sizes[i] == NB * NS * ND)      x = (const float*)d_in[i];
        else if (in_sizes[i] == NO * NS)      W = (const float*)d_in[i];
        else if (in_sizes[i] == NO)           bias = (const float*)d_in[i];
    }
    float* out = (float*)d_out;

    cudaFuncSetAttribute(fused, cudaFuncAttributeMaxDynamicSharedMemorySize,
                         SMEM_SZ);
    fused<<<dim3(16, NB), 256, SMEM_SZ>>>(x, W, bias, out);
}

// round 16
// speedup vs baseline: 1.0017x; 1.0017x over previous
#include <cuda_runtime.h>
#include <cuda_fp16.h>
#include <cstdint>

#define NB 16
#define NS 2048
#define ND 64
#define NO 128

// ---------------- scratch (no allocs allowed) ------------------------------
__device__ float    g_Y[NB * NO * ND];     // fp32 Y, RED-accumulated
__device__ unsigned g_bcnt[NB];            // per-batch barrier arrivals (0-init)
__device__ unsigned g_bep[NB];             // per-batch epochs (monotonic)

// ---------------- helpers --------------------------------------------------
__device__ __forceinline__ uint32_t smem_u32(const void* p) {
    uint32_t a;
    asm("{ .reg .u64 t; cvta.to.shared.u64 t, %1; cvt.u32.u64 %0, t; }"
        : "=r"(a) : "l"(p));
    return a;
}
__device__ __forceinline__ void ldm_x4(uint32_t* r, uint32_t addr) {
    asm volatile("ldmatrix.sync.aligned.m8n8.x4.shared.b16 {%0,%1,%2,%3}, [%4];"
                 : "=r"(r[0]), "=r"(r[1]), "=r"(r[2]), "=r"(r[3]) : "r"(addr));
}
__device__ __forceinline__ void ldm_x4t(uint32_t* r, uint32_t addr) {
    asm volatile("ldmatrix.sync.aligned.m8n8.x4.trans.shared.b16 {%0,%1,%2,%3}, [%4];"
                 : "=r"(r[0]), "=r"(r[1]), "=r"(r[2]), "=r"(r[3]) : "r"(addr));
}
__device__ __forceinline__ void mma_f16(float* c, const uint32_t* a,
                                        const uint32_t* b) {
    asm volatile(
        "mma.sync.aligned.m16n8k16.row.col.f32.f16.f16.f32 "
        "{%0,%1,%2,%3}, {%4,%5,%6,%7}, {%8,%9}, {%0,%1,%2,%3};"
        : "+f"(c[0]), "+f"(c[1]), "+f"(c[2]), "+f"(c[3])
        : "r"(a[0]), "r"(a[1]), "r"(a[2]), "r"(a[3]), "r"(b[0]), "r"(b[1]));
}
__device__ __forceinline__ void red_f32(float* p, float v) {
    asm volatile("red.global.add.f32 [%0], %1;" :: "l"(p), "f"(v) : "memory");
}
__device__ __forceinline__ uint32_t hpack2(float a, float b) {
    __half2 h = __floats2half2_rn(a, b);
    return *(uint32_t*)&h;
}

// Per-batch barrier over the 16 CTAs sharing blockIdx.y == b.
// All 256 CTAs are co-resident (2 CTAs/SM x 148 SMs = 296 >= 256), so the
// spin cannot deadlock. Epoch is monotonic across graph replays.
__device__ __forceinline__ void bbar(int b) {
    __threadfence();
    __syncthreads();
    if (threadIdx.x == 0) {
        unsigned my;
        asm volatile("ld.acquire.gpu.global.u32 %0, [%1];"
                     : "=r"(my) : "l"(&g_bep[b]));
        unsigned old = atomicAdd(&g_bcnt[b], 1);
        if (old == 15) {
            g_bcnt[b] = 0;
            asm volatile("red.release.gpu.global.add.u32 [%0], 1;"
                         :: "l"(&g_bep[b]) : "memory");
        } else {
            unsigned v;
            do {
                asm volatile("ld.acquire.gpu.global.u32 %0, [%1];"
                             : "=r"(v) : "l"(&g_bep[b]));
            } while (v == my);
        }
    }
    __syncthreads();
}

// smem layout (52KB, 2 CTAs/SM)
#define P1_WAHI 0
#define P1_XBHI 34816
#define P2_XHI  0
#define P2_YHI  18432
#define P2_BIAS 36864
#define SMEM_SZ 53248

// ===========================================================================
// Fused kernel, per-batch pipelines. grid (16 t, 16 b), 256 thr.
// CTA (t,b):  zero Y chunk -> bbar(b) -> P1 (W fp32 inline + x inline,
// HMMA, RED into g_Y[b]) -> bbar(b) -> P2 (x @ Y^T + bias).
// ===========================================================================
__global__ __launch_bounds__(256, 2) void fused(const float* __restrict__ x,
                                                const float* __restrict__ W,
                                                const float* __restrict__ bias,
                                                float* __restrict__ out) {
    extern __shared__ char sm[];
    const int tid = threadIdx.x, wid = tid >> 5, lane = tid & 31;
    const int t = blockIdx.x, b = blockIdx.y;
    const int wm = wid & 3, wn = wid >> 2;

    // ---- zero this CTA's chunk of g_Y[b] (128 float4) ----------------------
    if (tid < 128)
        ((float4*)g_Y)[b * 2048 + t * 128 + tid] = make_float4(0.f, 0.f, 0.f, 0.f);
    bbar(b);   // all 16 zeros of batch b done; hit at kernel start, tiny skew

    // ---------------- P1: g_Y[b] += W[:, kslice] @ x[b, kslice, :] ----------
    {
        const int o0 = wm * 32, d0 = wn * 32;
        const int kbase = t * 128;
        const uint32_t s_wahi = smem_u32(sm + P1_WAHI);
        const uint32_t s_xbhi = smem_u32(sm + P1_XBHI);

        // W slice [128 o][128 k] fp32 -> fp16 smem (16 f4/thread, 4 batches)
#pragma unroll
        for (int batch = 0; batch < 4; batch++) {
            float4 v[4];
#pragma unroll
            for (int j = 0; j < 4; j++) {
                int idx = tid + (batch * 4 + j) * 256;
                int o = idx >> 5, k4 = (idx & 31) * 4;
                v[j] = *(const float4*)(W + (size_t)o * NS + kbase + k4);
            }
#pragma unroll
            for (int j = 0; j < 4; j++) {
                int idx = tid + (batch * 4 + j) * 256;
                int o = idx >> 5, k4 = (idx & 31) * 4;
                *(uint2*)(sm + P1_WAHI + o * 272 + k4 * 2) =
                    make_uint2(hpack2(v[j].x, v[j].y), hpack2(v[j].z, v[j].w));
            }
        }
        // x slice [128 k][64 d] fp32 -> fp16 smem (8 f4/thread, 2 batches)
#pragma unroll
        for (int batch = 0; batch < 2; batch++) {
            float4 v[4];
#pragma unroll
            for (int j = 0; j < 4; j++) {
                int idx = tid + (batch * 4 + j) * 256;
                int k = idx >> 4, d4 = (idx & 15) * 4;
                v[j] = *(const float4*)(x + ((size_t)b * NS + kbase + k) * ND + d4);
            }
#pragma unroll
            for (int j = 0; j < 4; j++) {
                int idx = tid + (batch * 4 + j) * 256;
                int k = idx >> 4, d4 = (idx & 15) * 4;
                *(uint2*)(sm + P1_XBHI + k * 144 + d4 * 2) =
                    make_uint2(hpack2(v[j].x, v[j].y), hpack2(v[j].z, v[j].w));
            }
        }
        __syncthreads();

        float acc[2][4][4];
#pragma unroll
        for (int mt = 0; mt < 2; mt++)
#pragma unroll
            for (int nt = 0; nt < 4; nt++)
#pragma unroll
                for (int q = 0; q < 4; q++) acc[mt][nt][q] = 0.f;

#pragma unroll
        for (int kk = 0; kk < 8; kk++) {
            uint32_t ahi[2][4];
#pragma unroll
            for (int mt = 0; mt < 2; mt++) {
                uint32_t off = (uint32_t)((o0 + mt * 16 + (lane & 15)) * 272 +
                                          kk * 32 + (lane >> 4) * 16);
                ldm_x4(ahi[mt], s_wahi + off);
            }
            uint32_t bhi[2][4];
#pragma unroll
            for (int p = 0; p < 2; p++) {
                uint32_t off = (uint32_t)((kk * 16 + (lane & 15)) * 144 +
                                          (d0 + p * 16 + (lane >> 4) * 8) * 2);
                ldm_x4t(bhi[p], s_xbhi + off);
            }
#pragma unroll
            for (int mt = 0; mt < 2; mt++)
#pragma unroll
                for (int nt = 0; nt < 4; nt++)
                    mma_f16(acc[mt][nt], ahi[mt], &bhi[nt >> 1][(nt & 1) * 2]);
        }

        // RED-accumulate into g_Y[b]
        float* Yp = g_Y + (size_t)b * NO * ND;
#pragma unroll
        for (int mt = 0; mt < 2; mt++)
#pragma unroll
            for (int nt = 0; nt < 4; nt++) {
                int o = o0 + mt * 16 + (lane >> 2);
                int d = d0 + nt * 8 + (lane & 3) * 2;
                float* p = Yp + (size_t)o * ND + d;
                red_f32(p, acc[mt][nt][0]);
                red_f32(p + 1, acc[mt][nt][1]);
                red_f32(p + 8 * ND, acc[mt][nt][2]);
                red_f32(p + 8 * ND + 1, acc[mt][nt][3]);
            }
    }
    bbar(b);   // REDs of batch b complete + visible

    // ---------------- P2: out[b][s-tile t][o] = x @ Y^T + bias --------------
    {
        float* bias_s = (float*)(sm + P2_BIAS);
        const int s0 = t * 128;
        const int s0w = wm * 16, o0w = wn * 64;
        const uint32_t s_xhi = smem_u32(sm + P2_XHI);
        const uint32_t s_yhi = smem_u32(sm + P2_YHI);

        // x tile [128 s][64 d] fp32 — front-batched for MLP
        float4 xv[8];
#pragma unroll
        for (int j = 0; j < 8; j++) {
            int idx = tid + j * 256;
            int s = idx >> 4, d4 = (idx & 15) * 4;
            xv[j] = *(const float4*)(x + ((size_t)b * NS + s0 + s) * ND + d4);
        }
        // Y tile [128 o][64 d] fp32 (L2-hot from REDs)
        const float4* yg = (const float4*)(g_Y + (size_t)b * NO * ND);
#pragma unroll
        for (int j = 0; j < 8; j++) {
            int idx = tid + j * 256;
            int o = idx >> 4, d4 = (idx & 15) * 4;
            float4 v = yg[idx];
            *(uint2*)(sm + P2_YHI + o * 144 + d4 * 2) =
                make_uint2(hpack2(v.x, v.y), hpack2(v.z, v.w));
        }
#pragma unroll
        for (int j = 0; j < 8; j++) {
            int idx = tid + j * 256;
            int s = idx >> 4, d4 = (idx & 15) * 4;
            *(uint2*)(sm + P2_XHI + s * 144 + d4 * 2) =
                make_uint2(hpack2(xv[j].x, xv[j].y), hpack2(xv[j].z, xv[j].w));
        }
        if (tid < NO) bias_s[tid] = bias[tid];
        __syncthreads();

        float acc[2][8][4];
#pragma unroll
        for (int mt = 0; mt < 2; mt++)
#pragma unroll
            for (int nt = 0; nt < 8; nt++)
#pragma unroll
                for (int q = 0; q < 4; q++) acc[mt][nt][q] = 0.f;

#pragma unroll
        for (int kk = 0; kk < 4; kk++) {
            uint32_t ahi[2][4];
#pragma unroll
            for (int mt = 0; mt < 2; mt++) {
                uint32_t off = (uint32_t)((s0w + mt * 64 + (lane & 15)) * 144 +
                                          kk * 32 + (lane >> 4) * 16);
                ldm_x4(ahi[mt], s_xhi + off);
            }
            uint32_t bhi[4][4];
#pragma unroll
            for (int p = 0; p < 4; p++) {
                uint32_t off = (uint32_t)((o0w + p * 16 + (lane >> 4) * 8 + (lane & 7)) * 144 +
                                          kk * 32 + ((lane >> 3) & 1) * 16);
                ldm_x4(bhi[p], s_yhi + off);
            }
#pragma unroll
            for (int mt = 0; mt < 2; mt++)
#pragma unroll
                for (int nt = 0; nt < 8; nt++)
                    mma_f16(acc[mt][nt], ahi[mt], &bhi[nt >> 1][(nt & 1) * 2]);
        }

        // epilogue: +bias -> out
#pragma unroll
        for (int mt = 0; mt < 2; mt++) {
            const int srow = s0 + s0w + mt * 64 + (lane >> 2);
#pragma unroll
            for (int nt = 0; nt < 8; nt++) {
                int o = o0w + nt * 8 + (lane & 3) * 2;
                float2 bb = *(float2*)&bias_s[o];
                float* p0 = out + ((size_t)b * NS + srow) * NO + o;
                *(float2*)p0 =
                    make_float2(acc[mt][nt][0] + bb.x, acc[mt][nt][1] + bb.y);
                *(float2*)(p0 + 8 * NO) =
                    make_float2(acc[mt][nt][2] + bb.x, acc[mt][nt][3] + bb.y);
            }
        }
    }
}

// ===========================================================================
extern "C" void kernel_launch(void* const* d_in, const int* in_sizes, int n_in,
                              void* d_out, int out_size) {
    const float* x = nullptr;
    const float* W = nullptr;
    const float* bias = nullptr;
    for (int i = 0; i < n_in; i++) {
        if (in_sizes[i] == NB * NS * ND)      x = (const float*)d_in[i];
        else if (in_sizes[i] == NO * NS)      W = (const float*)d_in[i];
        else if (in_sizes[i] == NO)           bias = (const float*)d_in[i];
    }
    float* out = (float*)d_out;

    cudaFuncSetAttribute(fused, cudaFuncAttributeMaxDynamicSharedMemorySize,
                         SMEM_SZ);
    fused<<<dim3(16, NB), 256, SMEM_SZ>>>(x, W, bias, out);
}

// round 17
// speedup vs baseline: 1.0034x; 1.0017x over previous
#include <cuda_runtime.h>
#include <cuda_fp16.h>
#include <cstdint>

#define NB 16
#define NS 2048
#define ND 64
#define NO 128

// ---------------- scratch (no allocs allowed) ------------------------------
__device__ float    g_Ypart[NB * 16 * NO * ND];  // 8 MB fp32 partials [b][t]
__device__ __half   g_yh[NB * NO * ND];          // Y fp16 [b][o][d]
__device__ unsigned g_bcnt[NB];                  // per-batch barrier arrivals
__device__ unsigned g_bep[NB];                   // per-batch epochs (monotonic)

// ---------------- helpers --------------------------------------------------
__device__ __forceinline__ uint32_t smem_u32(const void* p) {
    uint32_t a;
    asm("{ .reg .u64 t; cvta.to.shared.u64 t, %1; cvt.u32.u64 %0, t; }"
        : "=r"(a) : "l"(p));
    return a;
}
__device__ __forceinline__ void ldm_x4(uint32_t* r, uint32_t addr) {
    asm volatile("ldmatrix.sync.aligned.m8n8.x4.shared.b16 {%0,%1,%2,%3}, [%4];"
                 : "=r"(r[0]), "=r"(r[1]), "=r"(r[2]), "=r"(r[3]) : "r"(addr));
}
__device__ __forceinline__ void ldm_x4t(uint32_t* r, uint32_t addr) {
    asm volatile("ldmatrix.sync.aligned.m8n8.x4.trans.shared.b16 {%0,%1,%2,%3}, [%4];"
                 : "=r"(r[0]), "=r"(r[1]), "=r"(r[2]), "=r"(r[3]) : "r"(addr));
}
__device__ __forceinline__ void mma_f16(float* c, const uint32_t* a,
                                        const uint32_t* b) {
    asm volatile(
        "mma.sync.aligned.m16n8k16.row.col.f32.f16.f16.f32 "
        "{%0,%1,%2,%3}, {%4,%5,%6,%7}, {%8,%9}, {%0,%1,%2,%3};"
        : "+f"(c[0]), "+f"(c[1]), "+f"(c[2]), "+f"(c[3])
        : "r"(a[0]), "r"(a[1]), "r"(a[2]), "r"(a[3]), "r"(b[0]), "r"(b[1]));
}
__device__ __forceinline__ uint32_t hpack2(float a, float b) {
    __half2 h = __floats2half2_rn(a, b);
    return *(uint32_t*)&h;
}

// Per-batch barrier over the 16 CTAs sharing blockIdx.y == b.
// All 256 CTAs co-resident (2 CTAs/SM x 148 = 296 >= 256): no deadlock.
// Epoch monotonic across graph replays.
__device__ __forceinline__ void bbar(int b) {
    __threadfence();
    __syncthreads();
    if (threadIdx.x == 0) {
        unsigned my;
        asm volatile("ld.acquire.gpu.global.u32 %0, [%1];"
                     : "=r"(my) : "l"(&g_bep[b]));
        unsigned old = atomicAdd(&g_bcnt[b], 1);
        if (old == 15) {
            g_bcnt[b] = 0;
            asm volatile("red.release.gpu.global.add.u32 [%0], 1;"
                         :: "l"(&g_bep[b]) : "memory");
        } else {
            unsigned v;
            do {
                asm volatile("ld.acquire.gpu.global.u32 %0, [%1];"
                             : "=r"(v) : "l"(&g_bep[b]));
            } while (v == my);
        }
    }
    __syncthreads();
}

// smem layout (52KB, 2 CTAs/SM)
#define P1_WAHI 0
#define P1_XBHI 34816
#define P2_XHI  0
#define P2_YHI  18432
#define P2_BIAS 36864
#define SMEM_SZ 53248

// ===========================================================================
// Fused kernel, per-batch pipelines, NO global atom，grid (16 t, 16 b).
// CTA (t,b): P1 (W+x inline fp16, HMMA, STG partial) -> bbar(b) ->
//            reduce slice (16 partials -> Y fp16) -> bbar(b) -> P2.
// ===========================================================================
__global__ __launch_bounds__(256, 2) void fused(const float* __restrict__ x,
                                                const float* __restrict__ W,
                                                const float* __restrict__ bias,
                                                float* __restrict__ out) {
    extern __shared__ char sm[];
    const int tid = threadIdx.x, wid = tid >> 5, lane = tid & 31;
    const int t = blockIdx.x, b = blockIdx.y;
    const int wm = wid & 3, wn = wid >> 2;

    // ---------------- P1: Ypart[b][t] = W[:, kslice] @ x[b, kslice, :] ------
    {
        const int o0 = wm * 32, d0 = wn * 32;
        const int kbase = t * 128;
        const uint32_t s_wahi = smem_u32(sm + P1_WAHI);
        const uint32_t s_xbhi = smem_u32(sm + P1_XBHI);

        // W slice [128 o][128 k] fp32 -> fp16 smem (16 f4/thread, 4 batches)
#pragma unroll
        for (int batch = 0; batch < 4; batch++) {
            float4 v[4];
#pragma unroll
            for (int j = 0; j < 4; j++) {
                int idx = tid + (batch * 4 + j) * 256;
                int o = idx >> 5, k4 = (idx & 31) * 4;
                v[j] = *(const float4*)(W + (size_t)o * NS + kbase + k4);
            }
#pragma unroll
            for (int j = 0; j < 4; j++) {
                int idx = tid + (batch * 4 + j) * 256;
                int o = idx >> 5, k4 = (idx & 31) * 4;
                *(uint2*)(sm + P1_WAHI + o * 272 + k4 * 2) =
                    make_uint2(hpack2(v[j].x, v[j].y), hpack2(v[j].z, v[j].w));
            }
        }
        // x slice [128 k][64 d] fp32 -> fp16 smem (8 f4/thread, 2 batches)
#pragma unroll
        for (int batch = 0; batch < 2; batch++) {
            float4 v[4];
#pragma unroll
            for (int j = 0; j < 4; j++) {
                int idx = tid + (batch * 4 + j) * 256;
                int k = idx >> 4, d4 = (idx & 15) * 4;
                v[j] = *(const float4*)(x + ((size_t)b * NS + kbase + k) * ND + d4);
            }
#pragma unroll
            for (int j = 0; j < 4; j++) {
                int idx = tid + (batch * 4 + j) * 256;
                int k = idx >> 4, d4 = (idx & 15) * 4;
                *(uint2*)(sm + P1_XBHI + k * 144 + d4 * 2) =
                    make_uint2(hpack2(v[j].x, v[j].y), hpack2(v[j].z, v[j].w));
            }
        }
        __syncthreads();

        float acc[2][4][4];
#pragma unroll
        for (int mt = 0; mt < 2; mt++)
#pragma unroll
            for (int nt = 0; nt < 4; nt++)
#pragma unroll
                for (int q = 0; q < 4; q++) acc[mt][nt][q] = 0.f;

#pragma unroll
        for (int kk = 0; kk < 8; kk++) {
            uint32_t ahi[2][4];
#pragma unroll
            for (int mt = 0; mt < 2; mt++) {
                uint32_t off = (uint32_t)((o0 + mt * 16 + (lane & 15)) * 272 +
                                          kk * 32 + (lane >> 4) * 16);
                ldm_x4(ahi[mt], s_wahi + off);
            }
            uint32_t bhi[2][4];
#pragma unroll
            for (int p = 0; p < 2; p++) {
                uint32_t off = (uint32_t)((kk * 16 + (lane & 15)) * 144 +
                                          (d0 + p * 16 + (lane >> 4) * 8) * 2);
                ldm_x4t(bhi[p], s_xbhi + off);
            }
#pragma unroll
            for (int mt = 0; mt < 2; mt++)
#pragma unroll
                for (int nt = 0; nt < 4; nt++)
                    mma_f16(acc[mt][nt], ahi[mt], &bhi[nt >> 1][(nt & 1) * 2]);
        }

        // STG partial tile (streaming, no atomics)
        float* Yp = g_Ypart + ((size_t)(b * 16 + t)) * (NO * ND);
#pragma unroll
        for (int mt = 0; mt < 2; mt++)
#pragma unroll
            for (int nt = 0; nt < 4; nt++) {
                int o = o0 + mt * 16 + (lane >> 2);
                int d = d0 + nt * 8 + (lane & 3) * 2;
                float* p = Yp + (size_t)o * ND + d;
                *(float2*)p = make_float2(acc[mt][nt][0], acc[mt][nt][1]);
                *(float2*)(p + 8 * ND) = make_float2(acc[mt][nt][2], acc[mt][nt][3]);
            }
    }
    bbar(b);   // all 16 partials of batch b written + visible

    // ---------------- inline reduce: 16 partials -> Y fp16 ------------------
    // CTA (t,b) owns float4 positions [t*128, t*128+128) of Y[b] (2048 total).
    if (tid < 128) {
        int pos = t * 128 + tid;
        const float4* pp = (const float4*)(g_Ypart + (size_t)b * 16 * NO * ND) + pos;
        float4 s = pp[0];
#pragma unroll
        for (int p = 1; p < 16; p++) {
            float4 v = pp[(size_t)p * 2048];
            s.x += v.x; s.y += v.y; s.z += v.z; s.w += v.w;
        }
        ((uint2*)g_yh)[b * 2048 + pos] =
            make_uint2(hpack2(s.x, s.y), hpack2(s.z, s.w));
    }
    bbar(b);   // Y[b] fp16 complete + visible

    // ---------------- P2: out[b][s-tile t][o] = x @ Y^T + bias --------------
    {
        float* bias_s = (float*)(sm + P2_BIAS);
        const int s0 = t * 128;
        const int s0w = wm * 16, o0w = wn * 64;
        const uint32_t s_xhi = smem_u32(sm + P2_XHI);
        const uint32_t s_yhi = smem_u32(sm + P2_YHI);

        // x tile [128 s][64 d] fp32 — front-batched for MLP
        float4 xv[8];
#pragma unroll
        for (int j = 0; j < 8; j++) {
            int idx = tid + j * 256;
            int s = idx >> 4, d4 = (idx & 15) * 4;
            xv[j] = *(const float4*)(x + ((size_t)b * NS + s0 + s) * ND + d4);
        }
        // Y tile [128 o][64 d] fp16 (L2-hot) — straight uint2 copies
        const uint2* yg = (const uint2*)g_yh + (size_t)b * 2048;
#pragma unroll
        for (int j = 0; j < 8; j++) {
            int idx = tid + j * 256;
            int o = idx >> 4, d4 = (idx & 15) * 4;
            *(uint2*)(sm + P2_YHI + o * 144 + d4 * 2) = yg[idx];
        }
#pragma unroll
        for (int j = 0; j < 8; j++) {
            int idx = tid + j * 256;
            int s = idx >> 4, d4 = (idx & 15) * 4;
            *(uint2*)(sm + P2_XHI + s * 144 + d4 * 2) =
                make_uint2(hpack2(xv[j].x, xv[j].y), hpack2(xv[j].z, xv[j].w));
        }
        if (tid < NO) bias_s[tid] = bias[tid];
        __syncthreads();

        float acc[2][8][4];
#pragma unroll
        for (int mt = 0; mt < 2; mt++)
#pragma unroll
            for (int nt = 0; nt < 8; nt++)
#pragma unroll
                for (int q = 0; q < 4; q++) acc[mt][nt][q] = 0.f;

#pragma unroll
        for (int kk = 0; kk < 4; kk++) {
            uint32_t ahi[2][4];
#pragma unroll
            for (int mt = 0; mt < 2; mt++) {
                uint32_t off = (uint32_t)((s0w + mt * 64 + (lane & 15)) * 144 +
                                          kk * 32 + (lane >> 4) * 16);
                ldm_x4(ahi[mt], s_xhi + off);
            }
            uint32_t bhi[4][4];
#pragma unroll
            for (int p = 0; p < 4; p++) {
                uint32_t off = (uint32_t)((o0w + p * 16 + (lane >> 4) * 8 + (lane & 7)) * 144 +
                                          kk * 32 + ((lane >> 3) & 1) * 16);
                ldm_x4(bhi[p], s_yhi + off);
            }
#pragma unroll
            for (int mt = 0; mt < 2; mt++)
#pragma unroll
                for (int nt = 0; nt < 8; nt++)
                    mma_f16(acc[mt][nt], ahi[mt], &bhi[nt >> 1][(nt & 1) * 2]);
        }

        // epilogue: +bias -> out
#pragma unroll
        for (int mt = 0; mt < 2; mt++) {
            const int srow = s0 + s0w + mt * 64 + (lane >> 2);
#pragma unroll
            for (int nt = 0; nt < 8; nt++) {
                int o = o0w + nt * 8 + (lane & 3) * 2;
                float2 bb = *(float2*)&bias_s[o];
                float* p0 = out + ((size_t)b * NS + srow) * NO + o;
                *(float2*)p0 =
                    make_float2(acc[mt][nt][0] + bb.x, acc[mt][nt][1] + bb.y);
                *(float2*)(p0 + 8 * NO) =
                    make_float2(acc[mt][nt][2] + bb.x, acc[mt][nt][3] + bb.y);
            }
        }
    }
}

// ===========================================================================
extern "C" void kernel_launch(void* const* d_in, const int* in_sizes, int n_in,
                              void* d_out, int out_size) {
    const float* x = nullptr;
    const float* W = nullptr;
    const float* bias = nullptr;
    for (int i = 0; i < n_in; i++) {
        if (in_sizes[i] == NB * NS * ND)      x = (const float*)d_in[i];
        else if (in_sizes[i] == NO * NS)      W = (const float*)d_in[i];
        else if (in_sizes[i] == NO)           bias = (const float*)d_in[i];
    }
    float* out = (float*)d_out;

    cudaFuncSetAttribute(fused, cudaFuncAttributeMaxDynamicSharedMemorySize,
                         SMEM_SZ);
    fused<<<dim3(16, NB), 256, SMEM_SZ>>>(x, W, bias, out);
}